// round 16
// baseline (speedup 1.0000x reference)
#include <cuda_runtime.h>
#include <cuda_bf16.h>
#include <cstdint>
#include <cstddef>

#define BSZ       64
#define SEQLEN    512
#define NSTEP     255              // sequential LSE steps per direction
#define NT        48
#define NT2       (NT * NT)
#define START_TAG 46
#define END_TAG   47
#define TPB       384              // 48 x 8
#define PD        4                // smem ring stages (power of 2, static)
#define ROWPF     52               // fwd pad: banks (20*sub+j)%32 distinct
#define ROWPB     56               // bwd pad: banks (24*i+sub)%32 distinct; >=48 => no overlap
#define STGF      (NT * 56)        // stage stride floats (max of both layouts)
#define STGB      (STGF * 4)       // 10752 B/stage; 4 stages = 43008 B static
#define NF4       (NT2 / 4)        // 576 float4 per tile
#define NCTA      (2 * BSZ)        // 128
#define SHP       8                // shrP row stride (6 used + 2 pad)

#define INV_LN2   1.4426950408889634f
#define LN2       0.6931471805599453f
#define OFF2      5.770780163555854f   // 4 / ln2

// Cross-CTA scratch.
__device__ float    g_fw[BSZ][NT + 1];   // [0..47]=v2_fwd (base-2), [48]=C2 offset
__device__ float    g_bw[BSZ][NT + 1];
__device__ float    g_ts[BSZ];
__device__ unsigned g_cnt = 0;           // completion counter (reset each launch)

__device__ __forceinline__ void cpa16(uint32_t dst, const void* src) {
    asm volatile("cp.async.cg.shared.global [%0], [%1], 16;\n" :: "r"(dst), "l"(src));
}
__device__ __forceinline__ void cpa_commit() {
    asm volatile("cp.async.commit_group;\n" ::: "memory");
}
template <int N>
__device__ __forceinline__ void cpa_wait() {
    asm volatile("cp.async.wait_group %0;\n" :: "n"(N) : "memory");
}
__device__ __forceinline__ float ex2f(float x) {
    float y;
    asm("ex2.approx.ftz.f32 %0, %1;" : "=f"(y) : "f"(x));
    return y;
}

// 128 CTAs: blockIdx.x = 2*b + dir. dir=0: forward over tiles 1..255 (+target
// score). dir=1: backward (beta) over tiles 511..256. 48-wide base-2 LSE
// recurrence: v2_k = log2(sum_i 2^(v2+tile/ln2)) - (v2_{k-1}[0]+4/ln2);
// true value = (v2 + C2) * ln2.
// Step structure (chain-minimized):
//   pre-barrier : 6 tile LDS into regs (stage published at barrier k-1;
//                 wait_group<1> keeps tile k+1 one barrier ahead)
//   barrier
//   post-barrier: refill issue, 1x LDS.128 + 1x LDS.64 from the PERMUTED
//                 v buffer shrP[s*8+k] = v[s+8k], FFMA+EX2, shfl-tree, LG2, STS
// The last CTA to finish performs the 64-batch combine and writes out[0].
__global__ __launch_bounds__(TPB, 1) void crf_main(
    const float* __restrict__ tr,
    const void*  __restrict__ tgt,
    float*       __restrict__ out)
{
    __shared__ __align__(16) float tile[PD][STGF];
    __shared__ __align__(16) float shrP[2][8 * SHP];   // permuted v, double-buffered
    __shared__ float ts_w[TPB / 32];    // per-warp target-score slots
    __shared__ unsigned s_rank;

    const int tid = threadIdx.x;
    const int b   = blockIdx.x >> 1;
    const int dir = blockIdx.x & 1;
    const int grp = tid >> 3;   // fwd: column j | bwd: row i
    const int sub = tid & 7;

    const float* __restrict__ tb = tr + (size_t)b * SEQLEN * NT2;

    const uint32_t tbase = (uint32_t)__cvta_generic_to_shared(&tile[0][0]);
    const int f1 = tid;
    const int f2 = tid + TPB;
    const int rowp = dir ? ROWPB : ROWPF;
    const uint32_t d1 = (uint32_t)((f1 / 12) * (rowp * 4) + (f1 % 12) * 16);
    const uint32_t d2 = (uint32_t)((f2 / 12) * (rowp * 4) + (f2 % 12) * 16);

    #define TILE_T(k) (dir ? (SEQLEN - 1 - (k)) : (k))

    if (tid < NT) {
        // init v_0 in base-2 units, permuted: shrP[(t&7)*8 + (t>>3)] = v[t]
        float v0 = INV_LN2 * (dir
            ? tb[(size_t)(SEQLEN - 1) * NT2 + tid * NT + END_TAG]  // beta_510
            : tb[START_TAG * NT + tid]);                            // forw_1
        shrP[0][(tid & 7) * SHP + (tid >> 3)] = v0;
    }

    // ---- prologue: stage tiles k = 1 .. PD-1 ----
    #pragma unroll
    for (int k = 1; k < PD; ++k) {
        uint32_t sb = tbase + (uint32_t)k * STGB;
        const char* s = (const char*)(tb + (size_t)TILE_T(k) * NT2);
        cpa16(sb + d1, s + (size_t)f1 * 16);
        if (tid < NF4 - TPB) cpa16(sb + d2, s + (size_t)f2 * 16);
        cpa_commit();
    }

    // ---- target path score (fwd CTA only; race-free per-warp slots) ----
    if (dir == 0) {
        // int64 probe: if target is int64 (values < 2^31), every odd 32-bit
        // word of the tensor head is zero (L1-broadcast read).
        const int* t32h = (const int*)tgt;
        int is64 = __all_sync(0xffffffffu, t32h[2 * (tid & 31) + 1] == 0);

        float ts = 0.0f;
        for (int s = tid; s < SEQLEN; s += TPB) {
            int cur, prv;
            if (is64) {
                const long long* t64 = (const long long*)tgt + (size_t)b * SEQLEN;
                cur = (int)t64[s];
                prv = (s == 0) ? START_TAG : (int)t64[s - 1];
            } else {
                const int* t32 = (const int*)tgt + b * SEQLEN;
                cur = t32[s];
                prv = (s == 0) ? START_TAG : t32[s - 1];
            }
            ts += tb[(size_t)s * NT2 + prv * NT + cur];
        }
        #pragma unroll
        for (int m = 16; m; m >>= 1) ts += __shfl_xor_sync(0xffffffffu, ts, m);
        if ((tid & 31) == 0) ts_w[tid >> 5] = ts;
    }

    // ---- per-thread tile read offsets (conflict-free) ----
    // fwd: tile[(sub+8k)*52 + j]   banks (20*sub+j)%32 distinct in warp
    // bwd: tile[i*56 + sub + 8k]   banks (24*i+sub)%32 distinct in warp
    const int step8 = dir ? 8 : (8 * ROWPF);
    const int q0 = dir ? (grp * ROWPB + sub) : (sub * ROWPF + grp);
    const int q1 = q0 + step8;
    const int q2 = q0 + 2 * step8;
    const int q3 = q0 + 3 * step8;
    const int q4 = q0 + 4 * step8;
    const int q5 = q0 + 5 * step8;

    // ---- strength-reduced loop pointers ----
    const long dstep = dir ? -(long)NT2 : (long)NT2;
    const float* src_rf = tb + (size_t)TILE_T(PD) * NT2;   // refill source, step 1
    uint32_t sb_rf = tbase;                                // stage PD&3 == 0
    const float* tlp = &tile[1][0];                        // consume stage, step 1
    const int wsts = (grp & 7) * SHP + (grp >> 3);         // permuted write slot

    float C2 = 0.0f;

    // ---- pre-loop: publish tiles 1,2 + shrP init ----
    cpa_wait<1>();       // tiles 1,2 complete (per-thread)
    __syncthreads();     // publish to all threads

    // ---- recurrence: k = 1 .. 255 ----
    for (int k = 1; k <= NSTEP; ++k) {
        // Pre-barrier: load tile-k operands into registers (stage k&3 was
        // published at barrier k-1; overlaps the previous step's shfl tail).
        const float* __restrict__ tl = tlp;
        const float t0 = tl[q0];
        const float t1 = tl[q1];
        const float t2 = tl[q2];
        const float t3 = tl[q3];
        const float t4 = tl[q4];
        const float t5 = tl[q5];
        tlp += STGF;
        if (tlp == &tile[0][0] + PD * STGF) tlp = &tile[0][0];

        cpa_wait<1>();   // tile k+1 complete (per-thread) — published below
        __syncthreads(); // publish tile k+1; order v_{k-1} stores

        // Refill freed stage with tile k+3 (post-barrier placement).
        if (k <= NSTEP - (PD - 1)) {
            const char* s = (const char*)src_rf;
            cpa16(sb_rf + d1, s + (size_t)f1 * 16);
            if (tid < NF4 - TPB) cpa16(sb_rf + d2, s + (size_t)f2 * 16);
        }
        cpa_commit();
        src_rf += dstep;
        sb_rf += STGB;
        if (sb_rf == tbase + PD * STGB) sb_rf = tbase;

        // v_{k-1} via permuted buffer: 6 consecutive floats per thread.
        const float4 rv  = *(const float4*)&shrP[(k + 1) & 1][sub * SHP];
        const float2 rv2 = *(const float2*)&shrP[(k + 1) & 1][sub * SHP + 4];

        float e0 = ex2f(fmaf(t0, INV_LN2, rv.x));
        float e1 = ex2f(fmaf(t1, INV_LN2, rv.y));
        float e2 = ex2f(fmaf(t2, INV_LN2, rv.z));
        float e3 = ex2f(fmaf(t3, INV_LN2, rv.w));
        float e4 = ex2f(fmaf(t4, INV_LN2, rv2.x));
        float e5 = ex2f(fmaf(t5, INV_LN2, rv2.y));

        float s = ((e0 + e1) + (e2 + e3)) + (e4 + e5);
        s += __shfl_xor_sync(0xffffffffu, s, 1);
        s += __shfl_xor_sync(0xffffffffu, s, 2);
        s += __shfl_xor_sync(0xffffffffu, s, 4);
        // writer lane (sub==0): rv.x == v_{k-1}[0]
        if (sub == 0) shrP[k & 1][wsts] = __log2f(s) - (rv.x + OFF2);
        if (tid == 0) C2 += rv.x + OFF2;   // accumulated base-2 offset
    }

    __syncthreads();
    {
        float* dst = dir ? g_bw[b] : g_fw[b];
        if (tid < NT) dst[tid] = shrP[NSTEP & 1][(tid & 7) * SHP + (tid >> 3)];
        if (tid == 0) {
            dst[NT] = C2;
            if (dir == 0) {
                float tss = 0.0f;
                #pragma unroll
                for (int w = 0; w < TPB / 32; ++w) tss += ts_w[w];
                g_ts[b] = tss;
            }
        }
    }

    // ---- last-CTA-done combine ----
    __threadfence();     // make this CTA's gmem stores visible gpu-wide
    __syncthreads();     // all fences done before the counter bump
    if (tid == 0) s_rank = atomicAdd(&g_cnt, 1u);
    __syncthreads();
    if (s_rank == NCTA - 1) {
        __threadfence(); // pair with writers' fences before reading g_*
        float loss = 0.0f;
        if (tid < BSZ) {
            const int bb = tid;
            float m = -1e30f;
            #pragma unroll 4
            for (int i = 0; i < NT; ++i) m = fmaxf(m, g_fw[bb][i] + g_bw[bb][i]);
            float s = 0.0f;
            #pragma unroll 4
            for (int i = 0; i < NT; ++i) s += ex2f(g_fw[bb][i] + g_bw[bb][i] - m);
            // back to natural log units
            float F = LN2 * (__log2f(s) + m + g_fw[bb][NT] + g_bw[bb][NT]);
            loss = F - g_ts[bb];
        }
        #pragma unroll
        for (int o = 16; o; o >>= 1) loss += __shfl_xor_sync(0xffffffffu, loss, o);
        if (tid == 0 || tid == 32) ts_w[tid >> 5] = loss;  // reuse smem
        __syncthreads();
        if (tid == 0) {
            out[0] = (ts_w[0] + ts_w[1]) * (1.0f / (float)BSZ);
            g_cnt = 0;   // reset for next graph replay
        }
    }
    #undef TILE_T
}

extern "C" void kernel_launch(void* const* d_in, const int* in_sizes, int n_in,
                              void* d_out, int out_size) {
    const void* trans = d_in[0];
    const void* tgt   = d_in[1];
    if (n_in >= 2 && in_sizes[0] < in_sizes[1]) {
        trans = d_in[1];
        tgt   = d_in[0];
    }
    crf_main<<<NCTA, TPB>>>((const float*)trans, tgt, (float*)d_out);
}

// round 17
// speedup vs baseline: 1.2380x; 1.2380x over previous
#include <cuda_runtime.h>
#include <cuda_bf16.h>
#include <cstdint>
#include <cstddef>

#define BSZ       64
#define SEQLEN    512
#define NSTEP     255              // sequential steps per direction
#define NT        48
#define NT2       (NT * NT)
#define START_TAG 46
#define END_TAG   47
#define TPB       384              // 48 x 8
#define PD        4                // smem ring stages (power of 2, static)
#define ROWPF     52               // fwd pad: banks (20*sub+j)%32 distinct
#define ROWPB     56               // bwd pad: banks (24*i+sub)%32 distinct; >=48 => no overlap
#define STGF      (NT * 56)        // stage stride floats (max of both layouts)
#define STGB      (STGF * 4)       // 10752 B/stage; 4 stages = 43008 B static
#define NF4       (NT2 / 4)        // 576 float4 per tile
#define NCTA      (2 * BSZ)        // 128

#define INV_LN2   1.4426950408889634f
#define LN2       0.6931471805599453f

// Cross-CTA scratch.
__device__ float    g_fw[BSZ][NT + 1];   // [0..47]=v2_fwd (base-2 log), [48]=C2
__device__ float    g_bw[BSZ][NT + 1];
__device__ float    g_ts[BSZ];
__device__ unsigned g_cnt = 0;           // completion counter (reset each launch)

__device__ __forceinline__ void cpa16(uint32_t dst, const void* src) {
    asm volatile("cp.async.cg.shared.global [%0], [%1], 16;\n" :: "r"(dst), "l"(src));
}
__device__ __forceinline__ void cpa_commit() {
    asm volatile("cp.async.commit_group;\n" ::: "memory");
}
__device__ __forceinline__ void cpa_wait2() {
    asm volatile("cp.async.wait_group %0;\n" :: "n"(PD - 2) : "memory");
}
__device__ __forceinline__ float ex2f(float x) {
    float y;
    asm("ex2.approx.ftz.f32 %0, %1;" : "=f"(y) : "f"(x));
    return y;
}

// 128 CTAs: blockIdx.x = 2*b + dir. dir=0: forward over tiles 1..255 (+target
// score). dir=1: backward (beta) over tiles 511..256.
// SCALED LINEAR-SPACE recurrence (scaled HMM forward algorithm):
//   state u = 2^v carried linearly in smem; per step
//     E[i][j] = 2^(T[i][j]/ln2)            <- independent of u (off-chain MUFU)
//     S_j     = sum_i u[i] * E[i][j]       <- FFMA tree + shfl (no MUFU!)
//     u'_j    = S_j * 2^(-e),  e = exponent of u[0] (writer lane's own rin[0];
//               exact power-of-2 renorm via integer ops; tid0: C2 += e)
//   log2 taken only once at the end. Mathematically identical to the base-2
//   LSE recurrence; u bounded ~2^[-14,19], products <= 2^31 (fp32-safe).
// Tiles stream through the proven 4-stage padded static-smem ring (coalesced
// 16B cp.async, wait_group<2>, post-barrier refill). Last CTA combines.
__global__ __launch_bounds__(TPB, 1) void crf_main(
    const float* __restrict__ tr,
    const void*  __restrict__ tgt,
    float*       __restrict__ out)
{
    __shared__ __align__(16) float tile[PD][STGF];
    __shared__ float shr[2][NT];        // u (linear space), double-buffered
    __shared__ float ts_w[TPB / 32];    // per-warp target-score slots
    __shared__ unsigned s_rank;

    const int tid = threadIdx.x;
    const int b   = blockIdx.x >> 1;
    const int dir = blockIdx.x & 1;
    const int grp = tid >> 3;   // fwd: column j | bwd: row i
    const int sub = tid & 7;

    const float* __restrict__ tb = tr + (size_t)b * SEQLEN * NT2;

    const uint32_t tbase = (uint32_t)__cvta_generic_to_shared(&tile[0][0]);
    const int f1 = tid;
    const int f2 = tid + TPB;
    const int rowp = dir ? ROWPB : ROWPF;
    const uint32_t d1 = (uint32_t)((f1 / 12) * (rowp * 4) + (f1 % 12) * 16);
    const uint32_t d2 = (uint32_t)((f2 / 12) * (rowp * 4) + (f2 % 12) * 16);

    #define TILE_T(k) (dir ? (SEQLEN - 1 - (k)) : (k))

    if (tid < NT) {
        // u_0 = 2^(T_init / ln2)
        float t0v = dir
            ? tb[(size_t)(SEQLEN - 1) * NT2 + tid * NT + END_TAG]  // beta_510
            : tb[START_TAG * NT + tid];                             // forw_1
        shr[0][tid] = ex2f(t0v * INV_LN2);
    }

    // ---- prologue: stage tiles k = 1 .. PD-1 ----
    #pragma unroll
    for (int k = 1; k < PD; ++k) {
        uint32_t sb = tbase + (uint32_t)k * STGB;
        const char* s = (const char*)(tb + (size_t)TILE_T(k) * NT2);
        cpa16(sb + d1, s + (size_t)f1 * 16);
        if (tid < NF4 - TPB) cpa16(sb + d2, s + (size_t)f2 * 16);
        cpa_commit();
    }

    // ---- target path score (fwd CTA only; race-free per-warp slots) ----
    if (dir == 0) {
        // int64 probe: if target is int64 (values < 2^31), every odd 32-bit
        // word of the tensor head is zero (L1-broadcast read).
        const int* t32h = (const int*)tgt;
        int is64 = __all_sync(0xffffffffu, t32h[2 * (tid & 31) + 1] == 0);

        float ts = 0.0f;
        for (int s = tid; s < SEQLEN; s += TPB) {
            int cur, prv;
            if (is64) {
                const long long* t64 = (const long long*)tgt + (size_t)b * SEQLEN;
                cur = (int)t64[s];
                prv = (s == 0) ? START_TAG : (int)t64[s - 1];
            } else {
                const int* t32 = (const int*)tgt + b * SEQLEN;
                cur = t32[s];
                prv = (s == 0) ? START_TAG : t32[s - 1];
            }
            ts += tb[(size_t)s * NT2 + prv * NT + cur];
        }
        #pragma unroll
        for (int m = 16; m; m >>= 1) ts += __shfl_xor_sync(0xffffffffu, ts, m);
        if ((tid & 31) == 0) ts_w[tid >> 5] = ts;
    }

    // ---- per-thread tile read offsets (conflict-free) ----
    // fwd: tile[(sub+8k)*52 + j]   banks (20*sub+j)%32 distinct in warp
    // bwd: tile[i*56 + sub + 8k]   banks (24*i+sub)%32 distinct in warp
    const int step8 = dir ? 8 : (8 * ROWPF);
    const int q0 = dir ? (grp * ROWPB + sub) : (sub * ROWPF + grp);
    const int q1 = q0 + step8;
    const int q2 = q0 + 2 * step8;
    const int q3 = q0 + 3 * step8;
    const int q4 = q0 + 4 * step8;
    const int q5 = q0 + 5 * step8;

    // ---- strength-reduced loop pointers ----
    const long dstep = dir ? -(long)NT2 : (long)NT2;
    const float* src_rf = tb + (size_t)TILE_T(PD) * NT2;   // refill source, step 1
    uint32_t sb_rf = tbase;                                // stage PD&3 == 0
    const float* tlp = &tile[1][0];                        // consume stage, step 1

    float C2 = 0.0f;   // accumulated base-2 exponent offset (tid0 only)

    // ---- recurrence: k = 1 .. 255 ----
    for (int k = 1; k <= NSTEP; ++k) {
        cpa_wait2();         // stage k copies complete (this thread)
        __syncthreads();     // cross-thread visibility; stage k-1 readers done

        // Refill freed stage with tile k+PD-1 (post-barrier placement).
        if (k <= NSTEP - (PD - 1)) {
            const char* s = (const char*)src_rf;
            cpa16(sb_rf + d1, s + (size_t)f1 * 16);
            if (tid < NF4 - TPB) cpa16(sb_rf + d2, s + (size_t)f2 * 16);
        }
        cpa_commit();
        src_rf += dstep;
        sb_rf += STGB;
        if (sb_rf == tbase + PD * STGB) sb_rf = tbase;

        const float* __restrict__ tl = tlp;
        tlp += STGF;
        if (tlp == &tile[0][0] + PD * STGF) tlp = &tile[0][0];

        // E = 2^(T/ln2): independent of u -> off the dependent chain.
        const float E0 = ex2f(tl[q0] * INV_LN2);
        const float E1 = ex2f(tl[q1] * INV_LN2);
        const float E2 = ex2f(tl[q2] * INV_LN2);
        const float E3 = ex2f(tl[q3] * INV_LN2);
        const float E4 = ex2f(tl[q4] * INV_LN2);
        const float E5 = ex2f(tl[q5] * INV_LN2);

        const float* __restrict__ rin = &shr[(k + 1) & 1][0];
        const float u0 = rin[sub];          // for sub==0 this is u[0]
        const float u1 = rin[sub +  8];
        const float u2 = rin[sub + 16];
        const float u3 = rin[sub + 24];
        const float u4 = rin[sub + 32];
        const float u5 = rin[sub + 40];

        // GEMV partial: product tree (fma pipe only, no MUFU)
        float p01 = fmaf(u1, E1, u0 * E0);
        float p23 = fmaf(u3, E3, u2 * E2);
        float p45 = fmaf(u5, E5, u4 * E4);
        float s = (p01 + p23) + p45;

        s += __shfl_xor_sync(0xffffffffu, s, 1);
        s += __shfl_xor_sync(0xffffffffu, s, 2);
        s += __shfl_xor_sync(0xffffffffu, s, 4);

        if (sub == 0) {
            // Exact power-of-2 renorm by exponent of u[0] (= this lane's u0,
            // positive normal float): u'_j = S_j * 2^(-e).
            unsigned ub = __float_as_uint(u0);
            int e = (int)(ub >> 23) - 127;
            float rsc = __uint_as_float((unsigned)(127 - e) << 23);
            shr[k & 1][grp] = s * rsc;
            if (tid == 0) C2 += (float)e;   // exact integer accumulation
        }
    }

    __syncthreads();
    {
        float* dst = dir ? g_bw[b] : g_fw[b];
        // back to base-2 log space for the combine
        if (tid < NT) dst[tid] = __log2f(shr[NSTEP & 1][tid]);
        if (tid == 0) {
            dst[NT] = C2;
            if (dir == 0) {
                float tss = 0.0f;
                #pragma unroll
                for (int w = 0; w < TPB / 32; ++w) tss += ts_w[w];
                g_ts[b] = tss;
            }
        }
    }

    // ---- last-CTA-done combine ----
    __threadfence();     // make this CTA's gmem stores visible gpu-wide
    __syncthreads();     // all fences done before the counter bump
    if (tid == 0) s_rank = atomicAdd(&g_cnt, 1u);
    __syncthreads();
    if (s_rank == NCTA - 1) {
        __threadfence(); // pair with writers' fences before reading g_*
        float loss = 0.0f;
        if (tid < BSZ) {
            const int bb = tid;
            float m = -1e30f;
            #pragma unroll 4
            for (int i = 0; i < NT; ++i) m = fmaxf(m, g_fw[bb][i] + g_bw[bb][i]);
            float s = 0.0f;
            #pragma unroll 4
            for (int i = 0; i < NT; ++i) s += ex2f(g_fw[bb][i] + g_bw[bb][i] - m);
            // back to natural log units
            float F = LN2 * (__log2f(s) + m + g_fw[bb][NT] + g_bw[bb][NT]);
            loss = F - g_ts[bb];
        }
        #pragma unroll
        for (int o = 16; o; o >>= 1) loss += __shfl_xor_sync(0xffffffffu, loss, o);
        if (tid == 0 || tid == 32) ts_w[tid >> 5] = loss;  // reuse smem
        __syncthreads();
        if (tid == 0) {
            out[0] = (ts_w[0] + ts_w[1]) * (1.0f / (float)BSZ);
            g_cnt = 0;   // reset for next graph replay
        }
    }
    #undef TILE_T
}

extern "C" void kernel_launch(void* const* d_in, const int* in_sizes, int n_in,
                              void* d_out, int out_size) {
    const void* trans = d_in[0];
    const void* tgt   = d_in[1];
    if (n_in >= 2 && in_sizes[0] < in_sizes[1]) {
        trans = d_in[1];
        tgt   = d_in[0];
    }
    crf_main<<<NCTA, TPB>>>((const float*)trans, tgt, (float*)d_out);
}